// round 13
// baseline (speedup 1.0000x reference)
#include <cuda_runtime.h>
#include <cstdint>

#define NBLOCKS   128
#define NTHREADS  256
#define BB        64
#define HH        1024
#define II        256
#define SS        512
#define OO        256
#define SI        (SS * II)

// ---------------- per-b-group barriers (4 groups x 32 CTAs) ----------------
__device__ unsigned g_bar_count[4 * 16];   // stride 16 -> 64B apart
__device__ unsigned g_bar_gen[4 * 16];

__device__ __forceinline__ void group_barrier(int bg, unsigned base_gen, unsigned step) {
    __syncthreads();
    if (threadIdx.x == 0) {
        unsigned* cnt = &g_bar_count[bg * 16];
        unsigned* gen = &g_bar_gen[bg * 16];
        __threadfence();
        unsigned prev = atomicAdd(cnt, 1u);
        if (prev == 31u) {
            *cnt = 0u;
            __threadfence();
            atomicAdd(gen, 1u);
        } else {
            while (*(volatile unsigned*)gen - base_gen < step) { }
        }
        __threadfence();
    }
    __syncthreads();
}

// ---------------- cp.async ----------------
__device__ __forceinline__ void cp_async16(uint32_t dst, const void* src) {
    asm volatile("cp.async.cg.shared.global [%0], [%1], 16;" :: "r"(dst), "l"(src));
}
__device__ __forceinline__ void cp_commit() {
    asm volatile("cp.async.commit_group;" ::: "memory");
}
template <int N>
__device__ __forceinline__ void cp_wait() {
    asm volatile("cp.async.wait_group %0;" :: "n"(N) : "memory");
}

// ---------------- tf32 helpers ----------------
__device__ __forceinline__ uint32_t f2tf32(float f) {
    uint32_t u;
    asm("cvt.rna.tf32.f32 %0, %1;" : "=r"(u) : "f"(f));
    return u;
}

// mma.sync m16n8k8 tf32: D += A(16x8, row) * B(8x8, col), fp32 accum.
__device__ __forceinline__ void mma_tf32(float* c,
                                         uint32_t a0, uint32_t a1, uint32_t a2, uint32_t a3,
                                         uint32_t b0, uint32_t b1) {
    asm volatile(
        "mma.sync.aligned.m16n8k8.row.col.f32.tf32.tf32.f32 "
        "{%0,%1,%2,%3},{%4,%5,%6,%7},{%8,%9},{%0,%1,%2,%3};"
        : "+f"(c[0]), "+f"(c[1]), "+f"(c[2]), "+f"(c[3])
        : "r"(a0), "r"(a1), "r"(a2), "r"(a3), "r"(b0), "r"(b1));
}

// ---------------- smem layout (bytes) ----------------
//   w_s    : 1280 k x 32 n x 4      = 163840  ([k][n], col rotated by (k&3)*8)
//   panels : 4 slots x 8 warps x (16 b x 20 fl) = 40960  (warp-private slices)
//   red    : 8 x 544 x 4            =  17408  ([warp][b*34 + n])
//   bias   : 128
static constexpr int OFF_W     = 0;
static constexpr int OFF_PAN   = 163840;
static constexpr int PAN_SLOT  = 8 * 16 * 20 * 4;          // 10240
static constexpr int WREG      = 16 * 20 * 4;              // 1280 per warp
static constexpr int OFF_RED   = OFF_PAN + 4 * PAN_SLOT;   // 204800
static constexpr int OFF_BIAS  = OFF_RED + 8 * 544 * 4;    // 222208
static constexpr int SMEM_BYTES = OFF_BIAS + 128;          // 222336

// Warp-private stage: this warp's 16b x 16k slice (64 chunks, 2 per lane).
__device__ __forceinline__ void stage_slice(const float* __restrict__ rowBase,
                                            int rowStrideFloats, uint32_t dstWarpBase,
                                            int lane) {
#pragma unroll
    for (int j = 0; j < 2; ++j) {
        int e = lane * 2 + j;                 // 0..63
        int b = e >> 2;                       // 0..15
        int c = e & 3;                        // 16B chunk within 16k
        cp_async16(dstWarpBase + (uint32_t)(b * 80 + c * 16),
                   rowBase + (size_t)b * rowStrideFloats + c * 4);
    }
    cp_commit();
}

__global__ void __launch_bounds__(NTHREADS, 1)
rnn_tc_kernel(const float* __restrict__ x,
              const float* __restrict__ wih,
              const float* __restrict__ whh,
              const float* __restrict__ bias,
              float* __restrict__ hstates)   // [S+1][B][H]
{
    extern __shared__ float smem_f[];
    char* smem = (char*)smem_f;
    const uint32_t sbase = (uint32_t)__cvta_generic_to_shared(smem);
    uint32_t* w_u    = (uint32_t*)(smem + OFF_W);
    float*    red_f  = (float*)(smem + OFF_RED);
    float*    bias_s = (float*)(smem + OFF_BIAS);

    const int tid  = threadIdx.x;
    const int lane = tid & 31;
    const int warp = tid >> 5;
    const int lq   = lane >> 2;      // 0..7
    const int lr   = lane & 3;       // 0..3
    const int ng   = blockIdx.x & 31;            // 32 n-groups of 32
    const int bg   = blockIdx.x >> 5;            // 4 b-groups of 16
    const int n0   = ng * 32;
    const int b0   = bg * 16;

    // Fill W: w(k, n0+n) -> w_u[k*32 + ((n + 8*(k&3)) & 31)], tf32-rounded.
    for (int i = tid; i < 32 * 1280; i += NTHREADS) {
        int n = i / 1280;
        int k = i - n * 1280;
        float v = (k < HH) ? whh[(size_t)(n0 + n) * HH + k]
                           : wih[(size_t)(n0 + n) * II + (k - HH)];
        w_u[k * 32 + ((n + 8 * (k & 3)) & 31)] = f2tf32(v);
    }
    if (tid < 32) bias_s[tid] = bias[n0 + tid];

    unsigned base_gen = *(volatile unsigned*)&g_bar_gen[bg * 16];

    const uint32_t wslot[4] = {
        sbase + OFF_PAN + 0 * PAN_SLOT + (uint32_t)warp * WREG,
        sbase + OFF_PAN + 1 * PAN_SLOT + (uint32_t)warp * WREG,
        sbase + OFF_PAN + 2 * PAN_SLOT + (uint32_t)warp * WREG,
        sbase + OFF_PAN + 3 * PAN_SLOT + (uint32_t)warp * WREG };
    const float* wslot_f[4] = {
        (const float*)(smem + OFF_PAN + 0 * PAN_SLOT) + warp * (WREG / 4),
        (const float*)(smem + OFF_PAN + 1 * PAN_SLOT) + warp * (WREG / 4),
        (const float*)(smem + OFF_PAN + 2 * PAN_SLOT) + warp * (WREG / 4),
        (const float*)(smem + OFF_PAN + 3 * PAN_SLOT) + warp * (WREG / 4) };

    const int wk = warp * 16;        // this warp's k offset within a 128-k panel

    // Prologue: stage the two x panels for t=0 (slots 0, 1).  [w_s not needed yet]
    stage_slice(x + (size_t)b0 * SI + (0 * 128 + wk), SI, wslot[0], lane);
    stage_slice(x + (size_t)b0 * SI + (1 * 128 + wk), SI, wslot[1], lane);
    __syncthreads();   // w_u / bias visible before compute

    unsigned bstep = 1;
    const int col0 = (lq + 8 * lr) & 31;   // rotated B column base (lane-constant)

#pragma unroll 1
    for (int t = 0; t < SS; ++t) {
        float C[16];
#pragma unroll
        for (int i = 0; i < 16; ++i) C[i] = 0.f;

        const float* hsrc = hstates + (size_t)t * (BB * HH) + (size_t)b0 * HH;

        // Panels: p0,p1 = x (k base 1024,1152); p2..p9 = h (k base 0..896).
#pragma unroll 1
        for (int p = 0; p < 10; ++p) {
            int next = p + 2;
            uint32_t nslot = wslot[(2 * t + next) & 3];
            if (next < 10) {
                stage_slice(hsrc + ((next - 2) * 128 + wk), HH, nslot, lane);
            } else {
                int tn = (t + 1 < SS) ? (t + 1) : t;
                stage_slice(x + (size_t)b0 * SI + (size_t)tn * II + ((next - 10) * 128 + wk),
                            SI, nslot, lane);
            }
            cp_wait<2>();
            __syncwarp();

            const float* panf = wslot_f[(2 * t + p) & 3];
            int kp_base = (p < 2) ? (1024 + p * 128) : ((p - 2) * 128);

#pragma unroll
            for (int it = 0; it < 2; ++it) {
                const float* ap = panf + lq * 20 + it * 8 + lr;
                uint32_t a0 = f2tf32(ap[0]);
                uint32_t a1 = f2tf32(ap[8 * 20]);
                uint32_t a2 = f2tf32(ap[4]);
                uint32_t a3 = f2tf32(ap[8 * 20 + 4]);
                const uint32_t* wb = w_u + (kp_base + wk + it * 8 + lr) * 32;
#pragma unroll
                for (int nt = 0; nt < 4; ++nt) {
                    int c = (col0 + nt * 8) & 31;
                    mma_tf32(C + nt * 4, a0, a1, a2, a3, wb[c], wb[128 + c]);
                }
            }
        }

        // Epilogue: warp partials -> red[warp][b*34 + n] (float2, 8B aligned).
        {
            float* rb = red_f + warp * 544;
#pragma unroll
            for (int nt = 0; nt < 4; ++nt) {
                int n = nt * 8 + 2 * lr;
                *(float2*)(rb + lq * 34 + n)       = make_float2(C[nt * 4 + 0], C[nt * 4 + 1]);
                *(float2*)(rb + (lq + 8) * 34 + n) = make_float2(C[nt * 4 + 2], C[nt * 4 + 3]);
            }
        }
        __syncthreads();

        // Sum 8 warps + bias, tanh, write hstates[t+1].
        {
            float* hout = hstates + (size_t)(t + 1) * (BB * HH);
#pragma unroll
            for (int rr = 0; rr < 2; ++rr) {
                int o = tid + rr * NTHREADS;      // 0..511
                int b = o >> 5, n = o & 31;
                float s = bias_s[n];
#pragma unroll
                for (int w = 0; w < 8; ++w) s += red_f[w * 544 + b * 34 + n];
                hout[(size_t)(b0 + b) * HH + n0 + n] = tanhf(s);
            }
        }

        group_barrier(bg, base_gen, bstep++);
    }
    cp_wait<0>();
}

// ---------------- init: zero h0 ----------------
__global__ void init_zero_kernel(float* __restrict__ hstates) {
    int i = blockIdx.x * blockDim.x + threadIdx.x;
    if (i < BB * HH) hstates[i] = 0.f;
}

// ---------------- final FC ----------------
__global__ void __launch_bounds__(256)
fc_kernel(const float* __restrict__ hlast,
          const float* __restrict__ fcw,
          const float* __restrict__ fcb,
          float* __restrict__ out)
{
    __shared__ float hrow[HH];
    int b = blockIdx.x;
    for (int i = threadIdx.x; i < HH; i += 256)
        hrow[i] = hlast[(size_t)b * HH + i];
    __syncthreads();

    int o = threadIdx.x;
    const float* w = fcw + (size_t)o * HH;
    float acc = 0.f;
#pragma unroll 4
    for (int k = 0; k < HH; k += 4) {
        float4 wv = *(const float4*)(w + k);
        acc = fmaf(hrow[k],     wv.x,
              fmaf(hrow[k + 1], wv.y,
              fmaf(hrow[k + 2], wv.z,
              fmaf(hrow[k + 3], wv.w, acc))));
    }
    out[(size_t)b * OO + o] = acc + fcb[o];
}

extern "C" void kernel_launch(void* const* d_in, const int* in_sizes, int n_in,
                              void* d_out, int out_size) {
    const float* x    = (const float*)d_in[0];   // [64,512,256]
    const float* wih  = (const float*)d_in[1];   // [1024,256]
    const float* whh  = (const float*)d_in[2];   // [1024,1024]
    const float* bias = (const float*)d_in[3];   // [1024]
    const float* fcw  = (const float*)d_in[4];   // [256,1024]
    const float* fcb  = (const float*)d_in[5];   // [256]

    float* out     = (float*)d_out;              // output [64,256]
    float* hstates = out + (size_t)BB * OO;      // hidden_states [513,64,1024]

    cudaFuncSetAttribute(rnn_tc_kernel,
                         cudaFuncAttributeMaxDynamicSharedMemorySize, SMEM_BYTES);

    init_zero_kernel<<<(BB * HH + 255) / 256, 256>>>(hstates);
    rnn_tc_kernel<<<NBLOCKS, NTHREADS, SMEM_BYTES>>>(x, wih, whh, bias, hstates);

    const float* hlast = hstates + (size_t)SS * (BB * HH);
    fc_kernel<<<BB, 256>>>(hlast, fcw, fcb, out);
}

// round 14
// speedup vs baseline: 1.1252x; 1.1252x over previous
#include <cuda_runtime.h>
#include <cstdint>

#define NBLOCKS   128
#define NTHREADS  512
#define BB        64
#define HH        1024
#define II        256
#define SS        512
#define OO        256
#define SI        (SS * II)

// ---------------- device scratch ----------------
__device__ float g_xt[BB * SI];          // x pre-converted to tf32 (rna), same layout
__device__ float g_ht[2][BB * HH];       // h as tf32 bits, double-buffered

// ---------------- per-b-group barriers (4 groups x 32 CTAs) ----------------
__device__ unsigned g_bar_count[4 * 16];
__device__ unsigned g_bar_gen[4 * 16];

__device__ __forceinline__ void group_barrier(int bg, unsigned base_gen, unsigned step) {
    __syncthreads();
    if (threadIdx.x == 0) {
        unsigned* cnt = &g_bar_count[bg * 16];
        unsigned* gen = &g_bar_gen[bg * 16];
        __threadfence();
        unsigned prev = atomicAdd(cnt, 1u);
        if (prev == 31u) {
            *cnt = 0u;
            __threadfence();
            atomicAdd(gen, 1u);
        } else {
            while (*(volatile unsigned*)gen - base_gen < step) { }
        }
        __threadfence();
    }
    __syncthreads();
}

// ---------------- cp.async ----------------
__device__ __forceinline__ void cp_async16(uint32_t dst, const void* src) {
    asm volatile("cp.async.cg.shared.global [%0], [%1], 16;" :: "r"(dst), "l"(src));
}
__device__ __forceinline__ void cp_commit() {
    asm volatile("cp.async.commit_group;" ::: "memory");
}
template <int N>
__device__ __forceinline__ void cp_wait() {
    asm volatile("cp.async.wait_group %0;" :: "n"(N) : "memory");
}

// ---------------- tf32 helpers ----------------
__device__ __forceinline__ uint32_t f2tf32(float f) {
    uint32_t u;
    asm("cvt.rna.tf32.f32 %0, %1;" : "=r"(u) : "f"(f));
    return u;
}

// mma.sync m16n8k8 tf32: D += A(16x8, row) * B(8x8, col), fp32 accum.
__device__ __forceinline__ void mma_tf32(float* c,
                                         uint32_t a0, uint32_t a1, uint32_t a2, uint32_t a3,
                                         uint32_t b0, uint32_t b1) {
    asm volatile(
        "mma.sync.aligned.m16n8k8.row.col.f32.tf32.tf32.f32 "
        "{%0,%1,%2,%3},{%4,%5,%6,%7},{%8,%9},{%0,%1,%2,%3};"
        : "+f"(c[0]), "+f"(c[1]), "+f"(c[2]), "+f"(c[3])
        : "r"(a0), "r"(a1), "r"(a2), "r"(a3), "r"(b0), "r"(b1));
}

// ---------------- smem layout (bytes) ----------------
//   w_s    : 1280 k x 32 n x 4   = 163840  ([k][n], col rotated by (k&3)*8)
//   panels : 4 x (16 x 132 x 4)  =  33792  ([b][k 0..127], row pad 132 floats)
//   red    : 16 x 528 x 4        =  33792  ([warp][b*33 + n], scalar stores)
//   bias   : 128
static constexpr int OFF_W    = 0;
static constexpr int OFF_PAN  = 163840;
static constexpr int PAN_BYTES = 16 * 132 * 4;            // 8448
static constexpr int OFF_RED  = OFF_PAN + 4 * PAN_BYTES;  // 197632
static constexpr int OFF_BIAS = OFF_RED + 16 * 528 * 4;   // 231424
static constexpr int SMEM_BYTES = OFF_BIAS + 128;         // 231552

// Stage one 16-row x 128-float panel (512 x 16B chunks, 1 per thread).
__device__ __forceinline__ void stage_panel(const float* __restrict__ srcRowBase,
                                            int rowStrideFloats, uint32_t dstBase) {
    int e   = threadIdx.x;                  // 0..511
    int row = e >> 5;                       // b 0..15
    int cc  = e & 31;                       // 16B chunk in row
    cp_async16(dstBase + (uint32_t)(row * 528 + cc * 16),
               srcRowBase + (size_t)row * rowStrideFloats + cc * 4);
    cp_commit();
}

__global__ void __launch_bounds__(NTHREADS, 1)
rnn_tc_kernel(const float* __restrict__ wih,
              const float* __restrict__ whh,
              const float* __restrict__ bias,
              float* __restrict__ hstates)   // [S+1][B][H]
{
    extern __shared__ float smem_f[];
    char* smem = (char*)smem_f;
    const uint32_t sbase = (uint32_t)__cvta_generic_to_shared(smem);
    uint32_t* w_u    = (uint32_t*)(smem + OFF_W);
    float*    red_f  = (float*)(smem + OFF_RED);
    float*    bias_s = (float*)(smem + OFF_BIAS);

    const int tid  = threadIdx.x;
    const int lane = tid & 31;
    const int warp = tid >> 5;            // 0..15
    const int lq   = lane >> 2;           // 0..7
    const int lr   = lane & 3;            // 0..3
    const int ng   = blockIdx.x & 31;     // 32 n-groups of 32
    const int bg   = blockIdx.x >> 5;     // 4 b-groups of 16
    const int n0   = ng * 32;
    const int b0   = bg * 16;
    const int kw   = warp * 8;            // this warp's k offset in a 128-k panel

    // Fill W: w(k, n0+n) -> w_u[k*32 + ((n + 8*(k&3)) & 31)], tf32-rounded.
    for (int i = tid; i < 32 * 1280; i += NTHREADS) {
        int n = i / 1280;
        int k = i - n * 1280;
        float v = (k < HH) ? whh[(size_t)(n0 + n) * HH + k]
                           : wih[(size_t)(n0 + n) * II + (k - HH)];
        w_u[k * 32 + ((n + 8 * (k & 3)) & 31)] = f2tf32(v);
    }
    if (tid < 32) bias_s[tid] = bias[n0 + tid];

    unsigned base_gen = *(volatile unsigned*)&g_bar_gen[bg * 16];

    // Prologue: stage the two x panels for t=0 into slots 0, 1.
    stage_panel(g_xt + (size_t)b0 * SI + 0 * 128, SI, sbase + OFF_PAN + 0 * PAN_BYTES);
    stage_panel(g_xt + (size_t)b0 * SI + 1 * 128, SI, sbase + OFF_PAN + 1 * PAN_BYTES);
    __syncthreads();   // w_u / bias visible

    unsigned bstep = 1;
    const int col0 = (lq + 8 * lr) & 31;  // rotated B column base (lane-constant)

#pragma unroll 1
    for (int t = 0; t < SS; ++t) {
        float C[16];
#pragma unroll
        for (int i = 0; i < 16; ++i) C[i] = 0.f;

        const float* hsrc = g_ht[t & 1] + (size_t)b0 * HH;

        // Panels: p0,p1 = x (k base 1024,1152); p2..p9 = h (k base 0..896).
#pragma unroll 1
        for (int p = 0; p < 10; ++p) {
            int next = p + 2;
            uint32_t nslot = sbase + OFF_PAN + (uint32_t)((2 * t + next) & 3) * PAN_BYTES;
            if (next < 10) {
                stage_panel(hsrc + (next - 2) * 128, HH, nslot);
            } else {
                int tn = (t + 1 < SS) ? (t + 1) : t;
                stage_panel(g_xt + (size_t)b0 * SI + (size_t)tn * II + (next - 10) * 128,
                            SI, nslot);
            }
            cp_wait<2>();
            __syncthreads();

            const uint32_t* panu = (const uint32_t*)(smem + OFF_PAN
                                   + (size_t)((2 * t + p) & 3) * PAN_BYTES);
            int kp_base = (p < 2) ? (1024 + p * 128) : ((p - 2) * 128);

            // One m16n8k8 k-slab per warp per panel (A already tf32 bits).
            const uint32_t* ap = panu + lq * 132 + kw + lr;
            uint32_t a0 = ap[0];
            uint32_t a1 = ap[8 * 132];
            uint32_t a2 = ap[4];
            uint32_t a3 = ap[8 * 132 + 4];
            const uint32_t* wb = w_u + (kp_base + kw + lr) * 32;
#pragma unroll
            for (int nt = 0; nt < 4; ++nt) {
                int c = (col0 + nt * 8) & 31;
                mma_tf32(C + nt * 4, a0, a1, a2, a3, wb[c], wb[128 + c]);
            }
        }

        // Epilogue: warp partials -> red[warp][b*33 + n] (scalar stores).
        {
            float* rb = red_f + warp * 528;
#pragma unroll
            for (int nt = 0; nt < 4; ++nt) {
                int n = nt * 8 + 2 * lr;
                rb[lq * 33 + n]           = C[nt * 4 + 0];
                rb[lq * 33 + n + 1]       = C[nt * 4 + 1];
                rb[(lq + 8) * 33 + n]     = C[nt * 4 + 2];
                rb[(lq + 8) * 33 + n + 1] = C[nt * 4 + 3];
            }
        }
        __syncthreads();

        // Sum 16 warps + bias, tanh; write hstates (fp32) + g_ht (tf32 bits).
        {
            float* hout = hstates + (size_t)(t + 1) * (BB * HH);
            float* htn  = g_ht[(t + 1) & 1];
            int o = tid;                      // 0..511
            int b = o >> 5, n = o & 31;
            float s = bias_s[n];
#pragma unroll
            for (int w = 0; w < 16; ++w) s += red_f[w * 528 + b * 33 + n];
            float hv = tanhf(s);
            size_t off = (size_t)(b0 + b) * HH + n0 + n;
            hout[off] = hv;
            htn[off] = __uint_as_float(f2tf32(hv));
        }

        group_barrier(bg, base_gen, bstep++);
    }
    cp_wait<0>();
}

// ---------------- prep: x -> tf32 (rna) ----------------
__global__ void convert_x_kernel(const float* __restrict__ x) {
    int i = blockIdx.x * blockDim.x + threadIdx.x;
    if (i < BB * SI) g_xt[i] = __uint_as_float(f2tf32(x[i]));
}

// ---------------- init: zero h0 ----------------
__global__ void init_zero_kernel(float* __restrict__ hstates) {
    int i = blockIdx.x * blockDim.x + threadIdx.x;
    if (i < BB * HH) {
        hstates[i] = 0.f;
        g_ht[0][i] = 0.f;
    }
}

// ---------------- final FC ----------------
__global__ void __launch_bounds__(256)
fc_kernel(const float* __restrict__ hlast,
          const float* __restrict__ fcw,
          const float* __restrict__ fcb,
          float* __restrict__ out)
{
    __shared__ float hrow[HH];
    int b = blockIdx.x;
    for (int i = threadIdx.x; i < HH; i += 256)
        hrow[i] = hlast[(size_t)b * HH + i];
    __syncthreads();

    int o = threadIdx.x;
    const float* w = fcw + (size_t)o * HH;
    float acc = 0.f;
#pragma unroll 4
    for (int k = 0; k < HH; k += 4) {
        float4 wv = *(const float4*)(w + k);
        acc = fmaf(hrow[k],     wv.x,
              fmaf(hrow[k + 1], wv.y,
              fmaf(hrow[k + 2], wv.z,
              fmaf(hrow[k + 3], wv.w, acc))));
    }
    out[(size_t)b * OO + o] = acc + fcb[o];
}

extern "C" void kernel_launch(void* const* d_in, const int* in_sizes, int n_in,
                              void* d_out, int out_size) {
    const float* x    = (const float*)d_in[0];   // [64,512,256]
    const float* wih  = (const float*)d_in[1];   // [1024,256]
    const float* whh  = (const float*)d_in[2];   // [1024,1024]
    const float* bias = (const float*)d_in[3];   // [1024]
    const float* fcw  = (const float*)d_in[4];   // [256,1024]
    const float* fcb  = (const float*)d_in[5];   // [256]

    float* out     = (float*)d_out;              // output [64,256]
    float* hstates = out + (size_t)BB * OO;      // hidden_states [513,64,1024]

    cudaFuncSetAttribute(rnn_tc_kernel,
                         cudaFuncAttributeMaxDynamicSharedMemorySize, SMEM_BYTES);

    convert_x_kernel<<<(BB * SI + 255) / 256, 256>>>(x);
    init_zero_kernel<<<(BB * HH + 255) / 256, 256>>>(hstates);

    rnn_tc_kernel<<<NBLOCKS, NTHREADS, SMEM_BYTES>>>(wih, whh, bias, hstates);

    const float* hlast = hstates + (size_t)SS * (BB * HH);
    fc_kernel<<<BB, 256>>>(hlast, fcw, fcb, out);
}

// round 16
// speedup vs baseline: 1.1310x; 1.0052x over previous
#include <cuda_runtime.h>
#include <cstdint>

#define NBLOCKS   128
#define NTHREADS  256
#define BB        64
#define HH        1024
#define II        256
#define SS        512
#define OO        256
#define SI        (SS * II)

// ---------------- device scratch ----------------
__device__ float g_xt[BB * SI];          // x pre-converted to tf32 (rna)
__device__ float g_ht[2][BB * HH];       // h as tf32 bits, double-buffered

// ---------------- per-b-group barrier state (4 groups x 32 CTAs) ----------------
__device__ unsigned g_bar_count[4 * 16];
__device__ unsigned g_bar_gen[4 * 16];

// ---------------- cp.async ----------------
__device__ __forceinline__ void cp_async16(uint32_t dst, const void* src) {
    asm volatile("cp.async.cg.shared.global [%0], [%1], 16;" :: "r"(dst), "l"(src));
}
__device__ __forceinline__ void cp_commit() {
    asm volatile("cp.async.commit_group;" ::: "memory");
}
template <int N>
__device__ __forceinline__ void cp_wait() {
    asm volatile("cp.async.wait_group %0;" :: "n"(N) : "memory");
}

// ---------------- tf32 helpers ----------------
__device__ __forceinline__ uint32_t f2tf32(float f) {
    uint32_t u;
    asm("cvt.rna.tf32.f32 %0, %1;" : "=r"(u) : "f"(f));
    return u;
}

// mma.sync m16n8k8 tf32: D += A(16x8, row) * B(8x8, col), fp32 accum.
__device__ __forceinline__ void mma_tf32(float* c,
                                         uint32_t a0, uint32_t a1, uint32_t a2, uint32_t a3,
                                         uint32_t b0, uint32_t b1) {
    asm volatile(
        "mma.sync.aligned.m16n8k8.row.col.f32.tf32.tf32.f32 "
        "{%0,%1,%2,%3},{%4,%5,%6,%7},{%8,%9},{%0,%1,%2,%3};"
        : "+f"(c[0]), "+f"(c[1]), "+f"(c[2]), "+f"(c[3])
        : "r"(a0), "r"(a1), "r"(a2), "r"(a3), "r"(b0), "r"(b1));
}

// ---------------- smem layout (bytes) ----------------
//   w_s    : 1280 k x 32 n x 4          = 163840  ([k][n], col rotated by (k&3)*8)
//   panels : 4 slots x 8 warps x 1280B  =  40960  (warp slice: 16b x 20fl, stride 20)
//   red    : 8 x 544 x 4                =  17408  ([warp][b*34 + n])
//   bias   : 128
static constexpr int OFF_W     = 0;
static constexpr int OFF_PAN   = 163840;
static constexpr int PAN_SLOT  = 8 * 1280;                 // 10240
static constexpr int OFF_RED   = OFF_PAN + 4 * PAN_SLOT;   // 204800
static constexpr int OFF_BIAS  = OFF_RED + 8 * 544 * 4;    // 222208
static constexpr int SMEM_BYTES = OFF_BIAS + 128;          // 222336

// Warp-private stage of a 16b x 16k slice via 16B cp.async.cg (L1-BYPASSING —
// required for cross-CTA coherence on the double-buffered g_ht).  Per instr:
// 8 rows x 64B contiguous (rows are 64B-aligned since kw*4 = warp*64).
__device__ __forceinline__ void stage_slice(const float* __restrict__ rowBase,
                                            int rowStrideFloats, uint32_t dstBase,
                                            int lane) {
    int rsub = lane >> 2;          // 0..7
    int c    = lane & 3;           // 16B chunk within 64B row slice
#pragma unroll
    for (int j = 0; j < 2; ++j) {
        int r = j * 8 + rsub;
        cp_async16(dstBase + (uint32_t)((r * 20 + c * 4) * 4),
                   rowBase + (size_t)r * rowStrideFloats + c * 4);
    }
    cp_commit();
}

__global__ void __launch_bounds__(NTHREADS, 1)
rnn_tc_kernel(const float* __restrict__ wih,
              const float* __restrict__ whh,
              const float* __restrict__ bias,
              float* __restrict__ hstates)   // [S+1][B][H]
{
    extern __shared__ float smem_f[];
    char* smem = (char*)smem_f;
    const uint32_t sbase = (uint32_t)__cvta_generic_to_shared(smem);
    uint32_t* w_u    = (uint32_t*)(smem + OFF_W);
    float*    red_f  = (float*)(smem + OFF_RED);
    float*    bias_s = (float*)(smem + OFF_BIAS);

    const int tid  = threadIdx.x;
    const int lane = tid & 31;
    const int warp = tid >> 5;            // 0..7
    const int lq   = lane >> 2;           // 0..7
    const int lr   = lane & 3;            // 0..3
    const int ng   = blockIdx.x & 31;     // 32 n-groups of 32
    const int bg   = blockIdx.x >> 5;     // 4 b-groups of 16
    const int n0   = ng * 32;
    const int b0   = bg * 16;
    const int kw   = warp * 16;           // warp's k offset within a 128-k panel

    // Fill W: w(k, n0+n) -> w_u[k*32 + ((n + 8*(k&3)) & 31)], tf32-rounded.
    for (int i = tid; i < 32 * 1280; i += NTHREADS) {
        int n = i / 1280;
        int k = i - n * 1280;
        float v = (k < HH) ? whh[(size_t)(n0 + n) * HH + k]
                           : wih[(size_t)(n0 + n) * II + (k - HH)];
        w_u[k * 32 + ((n + 8 * (k & 3)) & 31)] = f2tf32(v);
    }
    if (tid < 32) bias_s[tid] = bias[n0 + tid];

    volatile unsigned* genp = &g_bar_gen[bg * 16];
    unsigned* cntp = &g_bar_count[bg * 16];
    unsigned base_gen = *genp;

    // Warp-private slot bases (4-slot ring).
    uint32_t wslot[4];
    const uint32_t* wslot_u[4];
#pragma unroll
    for (int s = 0; s < 4; ++s) {
        wslot[s] = sbase + OFF_PAN + (uint32_t)s * PAN_SLOT + (uint32_t)warp * 1280u;
        wslot_u[s] = (const uint32_t*)(smem + OFF_PAN + s * PAN_SLOT + warp * 1280);
    }

    const float* xbase = g_xt + (size_t)b0 * SI + kw;

    // Prologue: stage this warp's slices of the two x panels for t=0.
    stage_slice(xbase + 0 * 128, SI, wslot[0], lane);
    stage_slice(xbase + 1 * 128, SI, wslot[1], lane);
    __syncthreads();   // w_u / bias visible

    const int col0 = (lq + 8 * lr) & 31;  // rotated B column base (lane-constant)

#pragma unroll 1
    for (int t = 0; t < SS; ++t) {
        float C[16];
#pragma unroll
        for (int i = 0; i < 16; ++i) C[i] = 0.f;

        const float* hbase = g_ht[t & 1] + (size_t)b0 * HH + kw;
        const float* xnext = xbase + (size_t)((t + 1 < SS) ? (t + 1) : t) * II;

#pragma unroll 1
        for (int p = 0; p < 10; ++p) {
            if (p == 0) {
                cp_wait<1>();              // x panel 0 resident
                __syncwarp();
            } else if (p == 1) {
                // h(t) is now required: wait for all 32 CTAs of this b-group.
                if (t > 0) {
                    while (*genp - base_gen < (unsigned)t) { }
                }
                stage_slice(hbase + 0 * 128, HH, wslot[(2 * t + 2) & 3], lane);
                stage_slice(hbase + 1 * 128, HH, wslot[(2 * t + 3) & 3], lane);
                cp_wait<2>();              // x panel 1 resident
                __syncwarp();
            } else {
                int nxt = p + 2;
                if (nxt < 10)
                    stage_slice(hbase + (nxt - 2) * 128, HH, wslot[(2 * t + nxt) & 3], lane);
                else
                    stage_slice(xnext + (nxt - 10) * 128, SI, wslot[(2 * t + nxt) & 3], lane);
                cp_wait<2>();              // panel p resident
                __syncwarp();
            }

            const uint32_t* panu = wslot_u[(2 * t + p) & 3];
            int kp_base = (p < 2) ? (1024 + p * 128) : ((p - 2) * 128);

#pragma unroll
            for (int it = 0; it < 2; ++it) {
                const uint32_t* ap = panu + lq * 20 + it * 8 + lr;
                uint32_t a0 = ap[0];
                uint32_t a1 = ap[8 * 20];
                uint32_t a2 = ap[4];
                uint32_t a3 = ap[8 * 20 + 4];
                const uint32_t* wb = w_u + (kp_base + kw + it * 8 + lr) * 32;
#pragma unroll
                for (int nt = 0; nt < 4; ++nt) {
                    int c = (col0 + nt * 8) & 31;
                    mma_tf32(C + nt * 4, a0, a1, a2, a3, wb[c], wb[128 + c]);
                }
            }
        }

        // Epilogue: warp partials -> red[warp][b*34 + n] (float2, 8B aligned).
        {
            float* rb = red_f + warp * 544;
#pragma unroll
            for (int nt = 0; nt < 4; ++nt) {
                int n = nt * 8 + 2 * lr;
                *(float2*)(rb + lq * 34 + n)       = make_float2(C[nt * 4 + 0], C[nt * 4 + 1]);
                *(float2*)(rb + (lq + 8) * 34 + n) = make_float2(C[nt * 4 + 2], C[nt * 4 + 3]);
            }
        }
        __syncthreads();

        // Sum 8 warps + bias, tanh; write hstates (fp32) + g_ht (tf32 bits).
        {
            float* hout = hstates + (size_t)(t + 1) * (BB * HH);
            float* htn  = g_ht[(t + 1) & 1];
#pragma unroll
            for (int rr = 0; rr < 2; ++rr) {
                int o = tid + rr * NTHREADS;      // 0..511
                int b = o >> 5, n = o & 31;
                float s = bias_s[n];
#pragma unroll
                for (int w = 0; w < 8; ++w) s += red_f[w * 544 + b * 34 + n];
                float hv = tanhf(s);
                size_t off = (size_t)(b0 + b) * HH + n0 + n;
                hout[off] = hv;
                htn[off] = __uint_as_float(f2tf32(hv));
            }
        }
        __threadfence();
        __syncthreads();

        // Arrive (release h(t+1)); wait is deferred into next step's panel loop.
        if (tid == 0) {
            unsigned prev = atomicAdd(cntp, 1u);
            if (prev == 31u) {
                *cntp = 0u;
                __threadfence();
                atomicAdd((unsigned*)genp, 1u);
            }
        }
    }
    cp_wait<0>();
}

// ---------------- prep: x -> tf32 (rna) ----------------
__global__ void convert_x_kernel(const float* __restrict__ x) {
    int i = blockIdx.x * blockDim.x + threadIdx.x;
    if (i < BB * SI) g_xt[i] = __uint_as_float(f2tf32(x[i]));
}

// ---------------- init: zero h0 ----------------
__global__ void init_zero_kernel(float* __restrict__ hstates) {
    int i = blockIdx.x * blockDim.x + threadIdx.x;
    if (i < BB * HH) {
        hstates[i] = 0.f;
        g_ht[0][i] = 0.f;
    }
}

// ---------------- final FC ----------------
__global__ void __launch_bounds__(256)
fc_kernel(const float* __restrict__ hlast,
          const float* __restrict__ fcw,
          const float* __restrict__ fcb,
          float* __restrict__ out)
{
    __shared__ float hrow[HH];
    int b = blockIdx.x;
    for (int i = threadIdx.x; i < HH; i += 256)
        hrow[i] = hlast[(size_t)b * HH + i];
    __syncthreads();

    int o = threadIdx.x;
    const float* w = fcw + (size_t)o * HH;
    float acc = 0.f;
#pragma unroll 4
    for (int k = 0; k < HH; k += 4) {
        float4 wv = *(const float4*)(w + k);
        acc = fmaf(hrow[k],     wv.x,
              fmaf(hrow[k + 1], wv.y,
              fmaf(hrow[k + 2], wv.z,
              fmaf(hrow[k + 3], wv.w, acc))));
    }
    out[(size_t)b * OO + o] = acc + fcb[o];
}

extern "C" void kernel_launch(void* const* d_in, const int* in_sizes, int n_in,
                              void* d_out, int out_size) {
    const float* x    = (const float*)d_in[0];   // [64,512,256]
    const float* wih  = (const float*)d_in[1];   // [1024,256]
    const float* whh  = (const float*)d_in[2];   // [1024,1024]
    const float* bias = (const float*)d_in[3];   // [1024]
    const float* fcw  = (const float*)d_in[4];   // [256,1024]
    const float* fcb  = (const float*)d_in[5];   // [256]

    float* out     = (float*)d_out;              // output [64,256]
    float* hstates = out + (size_t)BB * OO;      // hidden_states [513,64,1024]

    cudaFuncSetAttribute(rnn_tc_kernel,
                         cudaFuncAttributeMaxDynamicSharedMemorySize, SMEM_BYTES);

    convert_x_kernel<<<(BB * SI + 255) / 256, 256>>>(x);
    init_zero_kernel<<<(BB * HH + 255) / 256, 256>>>(hstates);

    rnn_tc_kernel<<<NBLOCKS, NTHREADS, SMEM_BYTES>>>(wih, whh, bias, hstates);

    const float* hlast = hstates + (size_t)SS * (BB * HH);
    fc_kernel<<<BB, 256>>>(hlast, fcw, fcb, out);
}

// round 17
// speedup vs baseline: 1.2625x; 1.1162x over previous
#include <cuda_runtime.h>
#include <cuda_fp16.h>
#include <cstdint>

#define NBLOCKS   128
#define NTHREADS  256
#define BB        64
#define HH        1024
#define II        256
#define SS        512
#define OO        256
#define SI        (SS * II)

// ---------------- device scratch ----------------
__device__ __half g_xh[BB * SI];         // x pre-converted to fp16
__device__ __half g_hh[2][BB * HH];      // h as fp16, double-buffered

// ---------------- per-b-group barriers (4 groups x 32 CTAs) ----------------
__device__ unsigned g_bar_count[4 * 16];
__device__ unsigned g_bar_gen[4 * 16];

__device__ __forceinline__ void group_barrier(int bg, unsigned base_gen, unsigned step) {
    __syncthreads();
    if (threadIdx.x == 0) {
        unsigned* cnt = &g_bar_count[bg * 16];
        unsigned* gen = &g_bar_gen[bg * 16];
        __threadfence();
        unsigned prev = atomicAdd(cnt, 1u);
        if (prev == 31u) {
            *cnt = 0u;
            __threadfence();
            atomicAdd(gen, 1u);
        } else {
            while (*(volatile unsigned*)gen - base_gen < step) { }
        }
        __threadfence();
    }
    __syncthreads();
}

// ---------------- cp.async ----------------
__device__ __forceinline__ void cp_async16(uint32_t dst, const void* src) {
    asm volatile("cp.async.cg.shared.global [%0], [%1], 16;" :: "r"(dst), "l"(src));
}
__device__ __forceinline__ void cp_commit() {
    asm volatile("cp.async.commit_group;" ::: "memory");
}
template <int N>
__device__ __forceinline__ void cp_wait() {
    asm volatile("cp.async.wait_group %0;" :: "n"(N) : "memory");
}

// mma.sync m16n8k16 fp16: D += A(16x16, row) * B(16x8, col), fp32 accum.
__device__ __forceinline__ void mma_f16(float* c,
                                        uint32_t a0, uint32_t a1, uint32_t a2, uint32_t a3,
                                        uint32_t b0, uint32_t b1) {
    asm volatile(
        "mma.sync.aligned.m16n8k16.row.col.f32.f16.f16.f32 "
        "{%0,%1,%2,%3},{%4,%5,%6,%7},{%8,%9},{%0,%1,%2,%3};"
        : "+f"(c[0]), "+f"(c[1]), "+f"(c[2]), "+f"(c[3])
        : "r"(a0), "r"(a1), "r"(a2), "r"(a3), "r"(b0), "r"(b1));
}

// ---------------- smem layout (bytes) ----------------
//   w_u    : 640 kp x 32 n x 4B  =  81920  (half2 per (kp,n); col rot by (kp&3)*8)
//   panels : 4 x (16 b x 68 w)x4 =  17408  ([b][kp], row stride 68 words)
//   red    : 8 x 544 x 4         =  17408  ([warp][b*34 + n])
//   bias   : 128
static constexpr int OFF_W    = 0;
static constexpr int OFF_PAN  = 81920;
static constexpr int PAN_BYTES = 16 * 68 * 4;             // 4352
static constexpr int OFF_RED  = OFF_PAN + 4 * PAN_BYTES;  // 99328
static constexpr int OFF_BIAS = OFF_RED + 8 * 544 * 4;    // 116736
static constexpr int SMEM_BYTES = OFF_BIAS + 128;         // 116864

// Stage one 16-row x 128-half panel (16B per thread; rows = 256B contiguous).
__device__ __forceinline__ void stage_panel(const __half* __restrict__ srcRowBase,
                                            int rowStrideHalves, uint32_t dstBase) {
    int e   = threadIdx.x;                  // 0..255
    int row = e >> 4;                       // b 0..15
    int cc  = e & 15;                       // 16B chunk (8 halves = 4 kp)
    cp_async16(dstBase + (uint32_t)((row * 68 + cc * 4) * 4),
               srcRowBase + (size_t)row * rowStrideHalves + cc * 8);
    cp_commit();
}

__global__ void __launch_bounds__(NTHREADS, 1)
rnn_tc_kernel(const float* __restrict__ wih,
              const float* __restrict__ whh,
              const float* __restrict__ bias,
              float* __restrict__ hstates)   // [S+1][B][H]
{
    extern __shared__ float smem_f[];
    char* smem = (char*)smem_f;
    const uint32_t sbase = (uint32_t)__cvta_generic_to_shared(smem);
    uint32_t* w_u    = (uint32_t*)(smem + OFF_W);
    float*    red_f  = (float*)(smem + OFF_RED);
    float*    bias_s = (float*)(smem + OFF_BIAS);

    const int tid  = threadIdx.x;
    const int lane = tid & 31;
    const int warp = tid >> 5;            // 0..7
    const int lq   = lane >> 2;           // 0..7
    const int lr   = lane & 3;            // 0..3
    const int ng   = blockIdx.x & 31;     // 32 n-groups of 32
    const int bg   = blockIdx.x >> 5;     // 4 b-groups of 16
    const int n0   = ng * 32;
    const int b0   = bg * 16;
    const int kpw  = warp * 8;            // warp's kp offset within a 64-kp panel

    // Fill W as half2 pairs: (k=2kp, 2kp+1) for n0+n, col rotated by (kp&3)*8.
    for (int i = tid; i < 32 * 640; i += NTHREADS) {
        int n  = i / 640;
        int kp = i - n * 640;
        int k  = kp * 2;
        float vlo, vhi;
        if (k < HH) {
            const float* r = whh + (size_t)(n0 + n) * HH + k;
            vlo = r[0]; vhi = r[1];
        } else {
            const float* r = wih + (size_t)(n0 + n) * II + (k - HH);
            vlo = r[0]; vhi = r[1];
        }
        __half2 p = __floats2half2_rn(vlo, vhi);
        w_u[kp * 32 + ((n + 8 * (kp & 3)) & 31)] = *(uint32_t*)&p;
    }
    if (tid < 32) bias_s[tid] = bias[n0 + tid];

    unsigned base_gen = *(volatile unsigned*)&g_bar_gen[bg * 16];

    // Prologue: stage the two x panels for t=0 into slots 0, 1.
    stage_panel(g_xh + (size_t)b0 * SI + 0 * 128, SI, sbase + OFF_PAN + 0 * PAN_BYTES);
    stage_panel(g_xh + (size_t)b0 * SI + 1 * 128, SI, sbase + OFF_PAN + 1 * PAN_BYTES);
    __syncthreads();   // w_u / bias visible

    unsigned bstep = 1;
    const int col0 = (lq + 8 * lr) & 31;  // rotated B column base (lane-constant)

#pragma unroll 1
    for (int t = 0; t < SS; ++t) {
        float C[16];
#pragma unroll
        for (int i = 0; i < 16; ++i) C[i] = 0.f;

        const __half* hsrc = g_hh[t & 1] + (size_t)b0 * HH;

        // Panels: p0,p1 = x (kp base 512,576); p2..p9 = h (kp base 0..448).
#pragma unroll 1
        for (int p = 0; p < 10; ++p) {
            int next = p + 2;
            uint32_t nslot = sbase + OFF_PAN + (uint32_t)((2 * t + next) & 3) * PAN_BYTES;
            if (next < 10) {
                stage_panel(hsrc + (next - 2) * 128, HH, nslot);
            } else {
                int tn = (t + 1 < SS) ? (t + 1) : t;
                stage_panel(g_xh + (size_t)b0 * SI + (size_t)tn * II + (next - 10) * 128,
                            SI, nslot);
            }
            cp_wait<2>();
            __syncthreads();

            const uint32_t* panu = (const uint32_t*)(smem + OFF_PAN
                                   + (size_t)((2 * t + p) & 3) * PAN_BYTES);
            int kp_base = ((p < 2) ? (512 + p * 64) : ((p - 2) * 64)) + kpw;

            // One m16n8k16 k-slab per warp per panel.
            const uint32_t* ap = panu + lq * 68 + kpw + lr;
            uint32_t a0 = ap[0];
            uint32_t a1 = ap[8 * 68];
            uint32_t a2 = ap[4];
            uint32_t a3 = ap[8 * 68 + 4];
            const uint32_t* wb = w_u + (kp_base + lr) * 32;
#pragma unroll
            for (int nt = 0; nt < 4; ++nt) {
                int c = (col0 + nt * 8) & 31;
                mma_f16(C + nt * 4, a0, a1, a2, a3, wb[c], wb[128 + c]);
            }
        }

        // Epilogue: warp partials -> red[warp][b*34 + n] (float2, 8B aligned).
        {
            float* rb = red_f + warp * 544;
#pragma unroll
            for (int nt = 0; nt < 4; ++nt) {
                int n = nt * 8 + 2 * lr;
                *(float2*)(rb + lq * 34 + n)       = make_float2(C[nt * 4 + 0], C[nt * 4 + 1]);
                *(float2*)(rb + (lq + 8) * 34 + n) = make_float2(C[nt * 4 + 2], C[nt * 4 + 3]);
            }
        }
        __syncthreads();

        // Sum 8 warps + bias, tanh; write hstates (fp32) + g_hh (fp16).
        {
            float*  hout = hstates + (size_t)(t + 1) * (BB * HH);
            __half* htn  = g_hh[(t + 1) & 1];
#pragma unroll
            for (int rr = 0; rr < 2; ++rr) {
                int o = tid + rr * NTHREADS;      // 0..511
                int b = o >> 5, n = o & 31;
                float s = bias_s[n];
#pragma unroll
                for (int w = 0; w < 8; ++w) s += red_f[w * 544 + b * 34 + n];
                float hv = tanhf(s);
                size_t off = (size_t)(b0 + b) * HH + n0 + n;
                hout[off] = hv;
                htn[off] = __float2half_rn(hv);
            }
        }
        __threadfence();

        group_barrier(bg, base_gen, bstep++);
    }
    cp_wait<0>();
}

// ---------------- prep: x -> fp16 ----------------
__global__ void convert_x_kernel(const float* __restrict__ x) {
    int i = blockIdx.x * blockDim.x + threadIdx.x;
    if (i < BB * SI) g_xh[i] = __float2half_rn(x[i]);
}

// ---------------- init: zero h0 ----------------
__global__ void init_zero_kernel(float* __restrict__ hstates) {
    int i = blockIdx.x * blockDim.x + threadIdx.x;
    if (i < BB * HH) {
        hstates[i] = 0.f;
        g_hh[0][i] = __float2half_rn(0.f);
    }
}

// ---------------- final FC ----------------
__global__ void __launch_bounds__(256)
fc_kernel(const float* __restrict__ hlast,
          const float* __restrict__ fcw,
          const float* __restrict__ fcb,
          float* __restrict__ out)
{
    __shared__ float hrow[HH];
    int b = blockIdx.x;
    for (int i = threadIdx.x; i < HH; i += 256)
        hrow[i] = hlast[(size_t)b * HH + i];
    __syncthreads();

    int o = threadIdx.x;
    const float* w = fcw + (size_t)o * HH;
    float acc = 0.f;
#pragma unroll 4
    for (int k = 0; k < HH; k += 4) {
        float4 wv = *(const float4*)(w + k);
        acc = fmaf(hrow[k],     wv.x,
              fmaf(hrow[k + 1], wv.y,
              fmaf(hrow[k + 2], wv.z,
              fmaf(hrow[k + 3], wv.w, acc))));
    }
    out[(size_t)b * OO + o] = acc + fcb[o];
}

extern "C" void kernel_launch(void* const* d_in, const int* in_sizes, int n_in,
                              void* d_out, int out_size) {
    const float* x    = (const float*)d_in[0];   // [64,512,256]
    const float* wih  = (const float*)d_in[1];   // [1024,256]
    const float* whh  = (const float*)d_in[2];   // [1024,1024]
    const float* bias = (const float*)d_in[3];   // [1024]
    const float* fcw  = (const float*)d_in[4];   // [256,1024]
    const float* fcb  = (const float*)d_in[5];   // [256]

    float* out     = (float*)d_out;              // output [64,256]
    float* hstates = out + (size_t)BB * OO;      // hidden_states [513,64,1024]

    cudaFuncSetAttribute(rnn_tc_kernel,
                         cudaFuncAttributeMaxDynamicSharedMemorySize, SMEM_BYTES);

    convert_x_kernel<<<(BB * SI + 255) / 256, 256>>>(x);
    init_zero_kernel<<<(BB * HH + 255) / 256, 256>>>(hstates);

    rnn_tc_kernel<<<NBLOCKS, NTHREADS, SMEM_BYTES>>>(wih, whh, bias, hstates);

    const float* hlast = hstates + (size_t)SS * (BB * HH);
    fc_kernel<<<BB, 256>>>(hlast, fcw, fcb, out);
}